// round 6
// baseline (speedup 1.0000x reference)
#include <cuda_runtime.h>
#include <cuda_fp16.h>

#define N_NODES 100000
#define N_EDGES 3200000
#define N_GRAPHS 1000
#define IN_DIM 10
#define HID 20
#define CAP 96
#define BN_EPS 1e-5f

#define TB 128
#define NBLK_N ((N_NODES + 255) / 256)
#define MAXBLK 3125   // ceil(100000/32)

// ---- device scratch ----
__device__ int    g_cur[N_NODES];
__device__ __align__(16) int g_src[N_NODES * CAP];     // row-major: g_src[i*CAP + k]
__device__ __align__(128) __half g_xh[N_NODES * 16];   // x half rows, 10 -> 16 (32B)
__device__ __align__(128) __half g_hh[N_NODES * 32];   // h half rows, 20 -> 32 (64B)
__device__ __align__(16)  float  g_tmp[N_NODES * HID]; // pre-BN activations (fp32)
__device__ float  g_bsum[MAXBLK * HID];
__device__ float  g_bsq[MAXBLK * HID];
__device__ float  g_ab[2 * HID];                       // folded BN: y*a + b

__global__ void k_zero_cur() {
    int i = blockIdx.x * blockDim.x + threadIdx.x;
    if (i < N_NODES) g_cur[i] = 0;
}

// 4 edges per thread via int4 loads
__global__ void k_fill4(const int* __restrict__ ei) {
    int e4 = blockIdx.x * blockDim.x + threadIdx.x;
    if (e4 * 4 >= N_EDGES) return;
    int4 s4 = ((const int4*)ei)[e4];
    int4 d4 = ((const int4*)(ei + N_EDGES))[e4];
    int ss[4] = {s4.x, s4.y, s4.z, s4.w};
    int dd[4] = {d4.x, d4.y, d4.z, d4.w};
#pragma unroll
    for (int q = 0; q < 4; q++) {
        int s = min(max(ss[q], 0), N_NODES - 1);
        int d = min(max(dd[q], 0), N_NODES - 1);
        int p = atomicAdd(&g_cur[d], 1);
        if (p < CAP) g_src[d * CAP + p] = s;
    }
}

// convert x (fp32, 10 dims) -> half rows padded to 16
__global__ void k_x2h(const float* __restrict__ x) {
    int i = blockIdx.x * blockDim.x + threadIdx.x;
    if (i >= N_NODES) return;
    const float2* xp = (const float2*)(x + (size_t)i * IN_DIM);
    __half2 h[8];
#pragma unroll
    for (int q = 0; q < 5; q++) { float2 v = xp[q]; h[q] = __floats2half2_rn(v.x, v.y); }
#pragma unroll
    for (int q = 5; q < 8; q++) h[q] = __floats2half2_rn(0.f, 0.f);
    int4* op = (int4*)(g_xh + (size_t)i * 16);
    op[0] = *(int4*)&h[0];
    op[1] = *(int4*)&h[4];
}

__device__ __forceinline__ void add_int4(float* acc, int4 v) {
    int w[4] = {v.x, v.y, v.z, v.w};
#pragma unroll
    for (int c = 0; c < 4; c++) {
        float2 f = __half22float2(*(__half2*)&w[c]);
        acc[c * 2]     += f.x;
        acc[c * 2 + 1] += f.y;
    }
}

// GRP adjacent lanes cooperate on one node; lane sub owns 8 dims (16B chunk).
// Neighbor indices read as int4 (4 at a time), uniform within the group -> broadcast.
// No shuffles in the edge loop; one shfl_xor reduction per node at the end.
template <int DR, int DP, int GRP>
__global__ void __launch_bounds__(TB) k_gin(const float* __restrict__ W,
                                            const float* __restrict__ bias) {
    const int SWS = 21;  // padded stride: sub offsets 0/8/16/24 banks -> conflict-free
    __shared__ float sW[32 * SWS];
    __shared__ float sb[HID];
    __shared__ float sws[4][HID];
    __shared__ float swq[4][HID];

    const __half* hin = (DR == IN_DIM) ? (const __half*)g_xh : (const __half*)g_hh;

    int t = threadIdx.x;
    for (int j = t; j < 32 * SWS; j += TB) sW[j] = 0.f;
    __syncthreads();
    for (int j = t; j < DR * HID; j += TB) {
        int d = j / HID, c = j % HID;
        sW[d * SWS + c] = W[j];
    }
    if (t < HID) sb[t] = bias[t];
    __syncthreads();

    const int sub = t & (GRP - 1);
    const int NPB = TB / GRP;
    int i = blockIdx.x * NPB + (t / GRP);
    bool active = (i < N_NODES);
    int ii = min(i, N_NODES - 1);

    float acc[8];
#pragma unroll
    for (int q = 0; q < 8; q++) acc[q] = 0.f;

    const bool ld = (sub * 8 < DP);
    if (ld) add_int4(acc, *(const int4*)(hin + (size_t)ii * DP + sub * 8));  // own row

    int deg = active ? min(g_cur[ii], CAP) : 0;
    const int4* sp4 = (const int4*)(g_src + (size_t)ii * CAP);
    for (int k = 0; k < deg; k += 4) {
        int4 idx = sp4[k >> 2];                 // broadcast within group
        int id[4] = {idx.x, idx.y, idx.z, idx.w};
#pragma unroll
        for (int j = 0; j < 4; j++) {
            if (k + j < deg && ld)
                add_int4(acc, *(const int4*)(hin + (size_t)id[j] * DP + sub * 8));
        }
    }

    // distributed GEMV: partial over this lane's 8 dims, xor-combine across group
    float y[HID];
#pragma unroll
    for (int j = 0; j < HID; j++) {
        float v = 0.f;
#pragma unroll
        for (int dl = 0; dl < 8; dl++)
            v += acc[dl] * sW[(sub * 8 + dl) * SWS + j];
#pragma unroll
        for (int o = GRP >> 1; o; o >>= 1)
            v += __shfl_xor_sync(0xffffffffu, v, o, GRP);
        y[j] = v + sb[j];
    }

    if (active && sub == 0) {
        float4* tp = (float4*)(g_tmp + (size_t)i * HID);
#pragma unroll
        for (int j = 0; j < 5; j++)
            tp[j] = make_float4(y[4*j], y[4*j+1], y[4*j+2], y[4*j+3]);
    }
    if (!active || sub != 0) {
#pragma unroll
        for (int j = 0; j < HID; j++) y[j] = 0.f;
    }

    // BN stats: warp shfl -> shared -> per-block float partials
    int lane = t & 31, wwid = t >> 5;
#pragma unroll
    for (int j = 0; j < HID; j++) {
        float s = y[j], q = y[j] * y[j];
#pragma unroll
        for (int o = 16; o; o >>= 1) {
            s += __shfl_down_sync(0xffffffff, s, o);
            q += __shfl_down_sync(0xffffffff, q, o);
        }
        if (lane == 0) { sws[wwid][j] = s; swq[wwid][j] = q; }
    }
    __syncthreads();
    if (t < HID) {
        float s = 0.f, q = 0.f;
#pragma unroll
        for (int w = 0; w < 4; w++) { s += sws[w][t]; q += swq[w][t]; }
        g_bsum[blockIdx.x * HID + t] = s;
        g_bsq[blockIdx.x * HID + t]  = q;
    }
}

// parallel partial reduce: warp w handles channel w; 2-way ILP double accumulation
__global__ void k_finalize(const float* __restrict__ g, const float* __restrict__ beta, int nblk) {
    int w = threadIdx.x >> 5, lane = threadIdx.x & 31;
    if (w >= HID) return;
    double s0 = 0.0, q0 = 0.0, s1 = 0.0, q1 = 0.0;
    for (int b = lane; b < nblk; b += 64) {
        s0 += (double)g_bsum[b * HID + w];
        q0 += (double)g_bsq[b * HID + w];
        int b2 = b + 32;
        if (b2 < nblk) {
            s1 += (double)g_bsum[b2 * HID + w];
            q1 += (double)g_bsq[b2 * HID + w];
        }
    }
    double s = s0 + s1, q = q0 + q1;
#pragma unroll
    for (int o = 16; o; o >>= 1) {
        s += __shfl_down_sync(0xffffffff, s, o);
        q += __shfl_down_sync(0xffffffff, q, o);
    }
    if (lane == 0) {
        float mu  = (float)(s / (double)N_NODES);
        float var = (float)(q / (double)N_NODES) - mu * mu;
        float a = rsqrtf(var + BN_EPS) * g[w];
        g_ab[w] = a;
        g_ab[HID + w] = beta[w] - mu * a;
    }
}

// normalize + relu -> half rows padded to 32 (64B)
__global__ void k_norm() {
    int i = blockIdx.x * blockDim.x + threadIdx.x;
    if (i >= N_NODES) return;
    const float4* tp = (const float4*)(g_tmp + (size_t)i * HID);
    __half2 h[16];
#pragma unroll
    for (int q = 0; q < 5; q++) {
        float4 v = tp[q];
        int j = 4 * q;
        float r0 = fmaxf(v.x * g_ab[j+0] + g_ab[HID+j+0], 0.f);
        float r1 = fmaxf(v.y * g_ab[j+1] + g_ab[HID+j+1], 0.f);
        float r2 = fmaxf(v.z * g_ab[j+2] + g_ab[HID+j+2], 0.f);
        float r3 = fmaxf(v.w * g_ab[j+3] + g_ab[HID+j+3], 0.f);
        h[2*q]   = __floats2half2_rn(r0, r1);
        h[2*q+1] = __floats2half2_rn(r2, r3);
    }
#pragma unroll
    for (int q = 10; q < 16; q++) h[q] = __floats2half2_rn(0.f, 0.f);
    int4* op = (int4*)(g_hh + (size_t)i * 32);
    op[0] = *(int4*)&h[0];
    op[1] = *(int4*)&h[4];
    op[2] = *(int4*)&h[8];
    op[3] = *(int4*)&h[12];
}

// warp per graph: binary-search node range (batch sorted), norm+relu+pool+fc
__global__ void k_pool_fc(const int* __restrict__ batch,
                          const float* __restrict__ fcW, const float* __restrict__ fcb,
                          float* __restrict__ out) {
    int gid = (blockIdx.x * blockDim.x + threadIdx.x) >> 5;
    int lane = threadIdx.x & 31;
    if (gid >= N_GRAPHS) return;

    int lo = 0, hi = N_NODES;
    while (lo < hi) { int mid = (lo + hi) >> 1; if (batch[mid] < gid) lo = mid + 1; else hi = mid; }
    int r0 = lo;
    hi = N_NODES;
    while (lo < hi) { int mid = (lo + hi) >> 1; if (batch[mid] < gid + 1) lo = mid + 1; else hi = mid; }
    int r1 = lo;

    float a = 0.f, b = 0.f, w0 = 0.f, w1 = 0.f;
    if (lane < HID) {
        a = g_ab[lane]; b = g_ab[HID + lane];
        w0 = fcW[lane * 2 + 0]; w1 = fcW[lane * 2 + 1];
    }
    float p0 = 0.f, p1 = 0.f;
    int n = r0;
    for (; n + 2 <= r1; n += 2) {
        float v0 = (lane < HID) ? g_tmp[(size_t)n * HID + lane] * a + b : 0.f;
        float v1 = (lane < HID) ? g_tmp[(size_t)(n + 1) * HID + lane] * a + b : 0.f;
        p0 += fmaxf(v0, 0.f);
        p1 += fmaxf(v1, 0.f);
    }
    if (n < r1) {
        float v = (lane < HID) ? g_tmp[(size_t)n * HID + lane] * a + b : 0.f;
        p0 += fmaxf(v, 0.f);
    }
    float pool = p0 + p1;
    float o0 = pool * w0, o1 = pool * w1;
#pragma unroll
    for (int o = 16; o; o >>= 1) {
        o0 += __shfl_down_sync(0xffffffff, o0, o);
        o1 += __shfl_down_sync(0xffffffff, o1, o);
    }
    if (lane == 0) {
        out[gid * 2 + 0] = o0 + fcb[0];
        out[gid * 2 + 1] = o1 + fcb[1];
    }
}

extern "C" void kernel_launch(void* const* d_in, const int* in_sizes, int n_in,
                              void* d_out, int out_size) {
    const float* x     = (const float*)d_in[0];
    const int*   ei    = (const int*)d_in[1];
    const int*   batch = (const int*)d_in[2];
    const float* W1  = (const float*)d_in[3];
    const float* b1  = (const float*)d_in[4];
    const float* g1  = (const float*)d_in[5];
    const float* be1 = (const float*)d_in[6];
    const float* W2  = (const float*)d_in[7];
    const float* b2  = (const float*)d_in[8];
    const float* g2  = (const float*)d_in[9];
    const float* be2 = (const float*)d_in[10];
    const float* W3  = (const float*)d_in[11];
    const float* b3  = (const float*)d_in[12];
    const float* g3  = (const float*)d_in[13];
    const float* be3 = (const float*)d_in[14];
    const float* fcW = (const float*)d_in[15];
    const float* fcb = (const float*)d_in[16];
    float* out = (float*)d_out;

    const int NB1 = (N_NODES + 63) / 64;   // GRP=2, TB=128: 64 nodes/block -> 1563
    const int NB2 = (N_NODES + 31) / 32;   // GRP=4, TB=128: 32 nodes/block -> 3125

    k_zero_cur<<<(N_NODES + 255) / 256, 256>>>();
    k_fill4<<<(N_EDGES / 4 + 255) / 256, 256>>>(ei);
    k_x2h<<<NBLK_N, 256>>>(x);

    // layer 1 (g_xh: 32B rows, 2-lane groups)
    k_gin<IN_DIM, 16, 2><<<NB1, TB>>>(W1, b1);
    k_finalize<<<1, 640>>>(g1, be1, NB1);
    k_norm<<<NBLK_N, 256>>>();

    // layer 2 (g_hh: 64B rows, 4-lane groups)
    k_gin<HID, 32, 4><<<NB2, TB>>>(W2, b2);
    k_finalize<<<1, 640>>>(g2, be2, NB2);
    k_norm<<<NBLK_N, 256>>>();

    // layer 3
    k_gin<HID, 32, 4><<<NB2, TB>>>(W3, b3);
    k_finalize<<<1, 640>>>(g3, be3, NB2);

    // norm + pool + fc fused (batch sorted -> contiguous ranges)
    k_pool_fc<<<(N_GRAPHS * 32 + 255) / 256, 256>>>(batch, fcW, fcb, out);
}

// round 8
// speedup vs baseline: 1.0435x; 1.0435x over previous
#include <cuda_runtime.h>

#define N_NODES 100000
#define N_EDGES 3200000
#define N_GRAPHS 1000
#define IN_DIM 10
#define HID 20
#define CAP 96
#define BN_EPS 1e-5f

#define NBLK_N ((N_NODES + 255) / 256)   // 391

// ---- device scratch ----
__device__ int g_cur[N_NODES];
__device__ __align__(16)  int   g_src[N_NODES * CAP];    // row-major: g_src[i*CAP + k]
__device__ __align__(128) float g_xpad[N_NODES * 16];    // x padded 10 -> 16 floats (64B rows)
__device__ __align__(128) float g_hpad[N_NODES * 32];    // h padded 20 -> 32 floats (128B rows)
__device__ __align__(16)  float g_agg[N_NODES * HID];    // gather output (dense)
__device__ __align__(16)  float g_tmp[N_NODES * HID];    // pre-BN activations
__device__ float g_bsum[NBLK_N * HID];
__device__ float g_bsq[NBLK_N * HID];
__device__ float g_ab[2 * HID];                          // folded BN: y*a + b

__global__ void k_zero_cur() {
    int i = blockIdx.x * blockDim.x + threadIdx.x;
    if (i < N_NODES) g_cur[i] = 0;
}

// 4 edges per thread via int4 loads; row-major neighbor lists
__global__ void k_fill4(const int* __restrict__ ei) {
    int e4 = blockIdx.x * blockDim.x + threadIdx.x;
    if (e4 * 4 >= N_EDGES) return;
    int4 s4 = ((const int4*)ei)[e4];
    int4 d4 = ((const int4*)(ei + N_EDGES))[e4];
    int ss[4] = {s4.x, s4.y, s4.z, s4.w};
    int dd[4] = {d4.x, d4.y, d4.z, d4.w};
#pragma unroll
    for (int q = 0; q < 4; q++) {
        int s = min(max(ss[q], 0), N_NODES - 1);
        int d = min(max(dd[q], 0), N_NODES - 1);
        int p = atomicAdd(&g_cur[d], 1);
        if (p < CAP) g_src[d * CAP + p] = s;
    }
}

// pad x rows 10 -> 16 floats
__global__ void k_xpad(const float* __restrict__ x) {
    int i = blockIdx.x * blockDim.x + threadIdx.x;
    if (i >= N_NODES * IN_DIM) return;
    int n = i / IN_DIM, d = i - n * IN_DIM;
    g_xpad[n * 16 + d] = x[i];
}

// Warp per node: lane j owns channel j. Indices preloaded coalesced into 3 regs,
// broadcast per edge via one shfl. 1 L1 wavefront per edge (padded rows).
// USE_X selects the input table INSIDE device code (device globals must not be
// passed as kernel args from host).
template <int DR, int ST, bool USE_X>
__global__ void __launch_bounds__(256) k_gather() {
    const float* __restrict__ hrow = USE_X ? g_xpad : g_hpad;
    int w = (blockIdx.x * 256 + threadIdx.x) >> 5;
    int lane = threadIdx.x & 31;
    if (w >= N_NODES) return;

    int deg = min(g_cur[w], CAP);
    const int* sp = g_src + (size_t)w * CAP;
    int i0 = sp[lane];
    int i1 = sp[32 + lane];
    int i2 = sp[64 + lane];

    float acc = 0.f;
    if (lane < DR) acc = hrow[(size_t)w * ST + lane];   // own row (eps = 0)

    int lim0 = min(deg, 32), lim1 = min(deg, 64);
#pragma unroll 4
    for (int e = 0; e < lim0; e++) {
        int s = __shfl_sync(0xffffffffu, i0, e);
        if (lane < DR) acc += hrow[(size_t)s * ST + lane];
    }
#pragma unroll 4
    for (int e = 32; e < lim1; e++) {
        int s = __shfl_sync(0xffffffffu, i1, e - 32);
        if (lane < DR) acc += hrow[(size_t)s * ST + lane];
    }
#pragma unroll 4
    for (int e = 64; e < deg; e++) {
        int s = __shfl_sync(0xffffffffu, i2, e - 64);
        if (lane < DR) acc += hrow[(size_t)s * ST + lane];
    }
    if (lane < DR) g_agg[(size_t)w * DR + lane] = acc;
}

// Thread per node: agg @ W + b -> g_tmp, per-block BN partials.
template <int DIN>
__global__ void __launch_bounds__(256) k_mlp(const float* __restrict__ W,
                                             const float* __restrict__ bias) {
    __shared__ float sW[DIN * HID];
    __shared__ float sb[HID];
    __shared__ float sws[8][HID];
    __shared__ float swq[8][HID];

    int t = threadIdx.x;
    for (int j = t; j < DIN * HID; j += 256) sW[j] = W[j];
    if (t < HID) sb[t] = bias[t];
    __syncthreads();

    int i = blockIdx.x * 256 + t;
    float y[HID];
#pragma unroll
    for (int j = 0; j < HID; j++) y[j] = 0.f;

    if (i < N_NODES) {
        float a[DIN];
        const float2* ap = (const float2*)(g_agg + (size_t)i * DIN);
#pragma unroll
        for (int q = 0; q < DIN / 2; q++) { float2 v = ap[q]; a[2*q] = v.x; a[2*q+1] = v.y; }
#pragma unroll
        for (int j = 0; j < HID; j++) {
            float v = sb[j];
#pragma unroll
            for (int d = 0; d < DIN; d++) v += a[d] * sW[d * HID + j];
            y[j] = v;
        }
        float4* tp = (float4*)(g_tmp + (size_t)i * HID);
#pragma unroll
        for (int j = 0; j < 5; j++)
            tp[j] = make_float4(y[4*j], y[4*j+1], y[4*j+2], y[4*j+3]);
    }

    int lane = t & 31, wwid = t >> 5;
#pragma unroll
    for (int j = 0; j < HID; j++) {
        float s = y[j], q = y[j] * y[j];
#pragma unroll
        for (int o = 16; o; o >>= 1) {
            s += __shfl_down_sync(0xffffffff, s, o);
            q += __shfl_down_sync(0xffffffff, q, o);
        }
        if (lane == 0) { sws[wwid][j] = s; swq[wwid][j] = q; }
    }
    __syncthreads();
    if (t < HID) {
        float s = 0.f, q = 0.f;
#pragma unroll
        for (int w = 0; w < 8; w++) { s += sws[w][t]; q += swq[w][t]; }
        g_bsum[blockIdx.x * HID + t] = s;
        g_bsq[blockIdx.x * HID + t]  = q;
    }
}

// parallel partial reduce: warp w handles channel w
__global__ void k_finalize(const float* __restrict__ g, const float* __restrict__ beta, int nblk) {
    int w = threadIdx.x >> 5, lane = threadIdx.x & 31;
    if (w >= HID) return;
    double s = 0.0, q = 0.0;
    for (int b = lane; b < nblk; b += 32) {
        s += (double)g_bsum[b * HID + w];
        q += (double)g_bsq[b * HID + w];
    }
#pragma unroll
    for (int o = 16; o; o >>= 1) {
        s += __shfl_down_sync(0xffffffff, s, o);
        q += __shfl_down_sync(0xffffffff, q, o);
    }
    if (lane == 0) {
        float mu  = (float)(s / (double)N_NODES);
        float var = (float)(q / (double)N_NODES) - mu * mu;
        float a = rsqrtf(var + BN_EPS) * g[w];
        g_ab[w] = a;
        g_ab[HID + w] = beta[w] - mu * a;
    }
}

// normalize + relu -> fp32 rows padded to 32 (128B)
__global__ void k_norm() {
    int i = blockIdx.x * blockDim.x + threadIdx.x;
    if (i >= N_NODES) return;
    const float4* tp = (const float4*)(g_tmp + (size_t)i * HID);
    float4* op = (float4*)(g_hpad + (size_t)i * 32);
#pragma unroll
    for (int q = 0; q < 5; q++) {
        float4 v = tp[q];
        int j = 4 * q;
        float4 r;
        r.x = fmaxf(v.x * g_ab[j+0] + g_ab[HID+j+0], 0.f);
        r.y = fmaxf(v.y * g_ab[j+1] + g_ab[HID+j+1], 0.f);
        r.z = fmaxf(v.z * g_ab[j+2] + g_ab[HID+j+2], 0.f);
        r.w = fmaxf(v.w * g_ab[j+3] + g_ab[HID+j+3], 0.f);
        op[q] = r;
    }
}

// warp per graph: binary-search node range (batch sorted), norm+relu+pool+fc
__global__ void k_pool_fc(const int* __restrict__ batch,
                          const float* __restrict__ fcW, const float* __restrict__ fcb,
                          float* __restrict__ out) {
    int gid = (blockIdx.x * blockDim.x + threadIdx.x) >> 5;
    int lane = threadIdx.x & 31;
    if (gid >= N_GRAPHS) return;

    int lo = 0, hi = N_NODES;
    while (lo < hi) { int mid = (lo + hi) >> 1; if (batch[mid] < gid) lo = mid + 1; else hi = mid; }
    int r0 = lo;
    hi = N_NODES;
    while (lo < hi) { int mid = (lo + hi) >> 1; if (batch[mid] < gid + 1) lo = mid + 1; else hi = mid; }
    int r1 = lo;

    float a = 0.f, b = 0.f, w0 = 0.f, w1 = 0.f;
    if (lane < HID) {
        a = g_ab[lane]; b = g_ab[HID + lane];
        w0 = fcW[lane * 2 + 0]; w1 = fcW[lane * 2 + 1];
    }
    float p0 = 0.f, p1 = 0.f;
    int n = r0;
    for (; n + 2 <= r1; n += 2) {
        float v0 = (lane < HID) ? g_tmp[(size_t)n * HID + lane] * a + b : 0.f;
        float v1 = (lane < HID) ? g_tmp[(size_t)(n + 1) * HID + lane] * a + b : 0.f;
        p0 += fmaxf(v0, 0.f);
        p1 += fmaxf(v1, 0.f);
    }
    if (n < r1) {
        float v = (lane < HID) ? g_tmp[(size_t)n * HID + lane] * a + b : 0.f;
        p0 += fmaxf(v, 0.f);
    }
    float pool = p0 + p1;
    float o0 = pool * w0, o1 = pool * w1;
#pragma unroll
    for (int o = 16; o; o >>= 1) {
        o0 += __shfl_down_sync(0xffffffff, o0, o);
        o1 += __shfl_down_sync(0xffffffff, o1, o);
    }
    if (lane == 0) {
        out[gid * 2 + 0] = o0 + fcb[0];
        out[gid * 2 + 1] = o1 + fcb[1];
    }
}

extern "C" void kernel_launch(void* const* d_in, const int* in_sizes, int n_in,
                              void* d_out, int out_size) {
    const float* x     = (const float*)d_in[0];
    const int*   ei    = (const int*)d_in[1];
    const int*   batch = (const int*)d_in[2];
    const float* W1  = (const float*)d_in[3];
    const float* b1  = (const float*)d_in[4];
    const float* g1  = (const float*)d_in[5];
    const float* be1 = (const float*)d_in[6];
    const float* W2  = (const float*)d_in[7];
    const float* b2  = (const float*)d_in[8];
    const float* g2  = (const float*)d_in[9];
    const float* be2 = (const float*)d_in[10];
    const float* W3  = (const float*)d_in[11];
    const float* b3  = (const float*)d_in[12];
    const float* g3  = (const float*)d_in[13];
    const float* be3 = (const float*)d_in[14];
    const float* fcW = (const float*)d_in[15];
    const float* fcb = (const float*)d_in[16];
    float* out = (float*)d_out;

    const int GB = (N_NODES * 32 + 255) / 256;   // 12500 blocks, warp per node

    k_zero_cur<<<NBLK_N, 256>>>();
    k_fill4<<<(N_EDGES / 4 + 255) / 256, 256>>>(ei);
    k_xpad<<<(N_NODES * IN_DIM + 255) / 256, 256>>>(x);

    // layer 1
    k_gather<IN_DIM, 16, true><<<GB, 256>>>();
    k_mlp<IN_DIM><<<NBLK_N, 256>>>(W1, b1);
    k_finalize<<<1, 640>>>(g1, be1, NBLK_N);
    k_norm<<<NBLK_N, 256>>>();

    // layer 2
    k_gather<HID, 32, false><<<GB, 256>>>();
    k_mlp<HID><<<NBLK_N, 256>>>(W2, b2);
    k_finalize<<<1, 640>>>(g2, be2, NBLK_N);
    k_norm<<<NBLK_N, 256>>>();

    // layer 3
    k_gather<HID, 32, false><<<GB, 256>>>();
    k_mlp<HID><<<NBLK_N, 256>>>(W3, b3);
    k_finalize<<<1, 640>>>(g3, be3, NBLK_N);

    // norm + pool + fc fused (batch sorted -> contiguous ranges)
    k_pool_fc<<<(N_GRAPHS * 32 + 255) / 256, 256>>>(batch, fcW, fcb, out);
}

// round 9
// speedup vs baseline: 1.2092x; 1.1587x over previous
#include <cuda_runtime.h>
#include <cuda_fp16.h>

#define N_NODES 100000
#define N_EDGES 3200000
#define N_GRAPHS 1000
#define IN_DIM 10
#define HID 20
#define CAP 96
#define BN_EPS 1e-5f

#define NBLK_N ((N_NODES + 255) / 256)     // 391
#define NBLK2  ((N_NODES * 2 + 255) / 256) // 782 (two threads per node)

// ---- device scratch ----
__device__ int g_cur[N_NODES];
__device__ __align__(16)  int    g_src[N_NODES * CAP];   // row-major: g_src[i*CAP + k]
__device__ int g_hist[128];
__device__ int g_off[128];
__device__ int g_perm[N_NODES];                          // degree-sorted node order
__device__ __align__(128) __half g_xh[N_NODES * 16];     // x half rows, 10 -> 16 (32B)
__device__ __align__(128) __half g_hh[N_NODES * 32];     // h half rows, 20 -> pad stride 32 (64B)
__device__ __align__(16)  float  g_tmp[N_NODES * HID];   // pre-BN activations (fp32)
__device__ float g_bsum[NBLK2 * HID];
__device__ float g_bsq[NBLK2 * HID];
__device__ float g_ab[2 * HID];                          // folded BN: y*a + b

__global__ void k_zero_cur() {
    int i = blockIdx.x * blockDim.x + threadIdx.x;
    if (i < N_NODES) g_cur[i] = 0;
    if (i < 128) { g_hist[i] = 0; }
}

// 4 edges per thread via int4 loads
__global__ void k_fill4(const int* __restrict__ ei) {
    int e4 = blockIdx.x * blockDim.x + threadIdx.x;
    if (e4 * 4 >= N_EDGES) return;
    int4 s4 = ((const int4*)ei)[e4];
    int4 d4 = ((const int4*)(ei + N_EDGES))[e4];
    int ss[4] = {s4.x, s4.y, s4.z, s4.w};
    int dd[4] = {d4.x, d4.y, d4.z, d4.w};
#pragma unroll
    for (int q = 0; q < 4; q++) {
        int s = min(max(ss[q], 0), N_NODES - 1);
        int d = min(max(dd[q], 0), N_NODES - 1);
        int p = atomicAdd(&g_cur[d], 1);
        if (p < CAP) g_src[d * CAP + p] = s;
    }
}

// convert x -> half rows padded to 16 halfs (32B)
__global__ void k_x2h(const float* __restrict__ x) {
    int i = blockIdx.x * blockDim.x + threadIdx.x;
    if (i >= N_NODES) return;
    const float2* xp = (const float2*)(x + (size_t)i * IN_DIM);
    __half2 h[8];
#pragma unroll
    for (int q = 0; q < 5; q++) { float2 v = xp[q]; h[q] = __floats2half2_rn(v.x, v.y); }
#pragma unroll
    for (int q = 5; q < 8; q++) h[q] = __floats2half2_rn(0.f, 0.f);
    int4* op = (int4*)(g_xh + (size_t)i * 16);
    op[0] = *(int4*)&h[0];
    op[1] = *(int4*)&h[4];
}

// ---- degree counting sort ----
__global__ void k_hist() {
    int i = blockIdx.x * blockDim.x + threadIdx.x;
    if (i < N_NODES) atomicAdd(&g_hist[min(g_cur[i], CAP)], 1);
}
__global__ void k_scan() {
    if (threadIdx.x == 0) {
        int acc = 0;
        for (int b = 0; b < 128; b++) { g_off[b] = acc; acc += g_hist[b]; }
    }
}
__global__ void k_scatter() {
    int i = blockIdx.x * blockDim.x + threadIdx.x;
    if (i < N_NODES) {
        int p = atomicAdd(&g_off[min(g_cur[i], CAP)], 1);
        g_perm[p] = i;
    }
}

template <int DR, int DP, int NLD>
__device__ __forceinline__ void add_row(float* acc, const __half* __restrict__ hin, int s) {
#pragma unroll
    for (int q = 0; q < NLD; q++) {
        int4 v = *(const int4*)(hin + (size_t)s * DP + q * 8);
        int w[4] = {v.x, v.y, v.z, v.w};
#pragma unroll
        for (int c = 0; c < 4; c++) {
            int base = q * 8 + c * 2;
            if (base < DR) {
                float2 f = __half22float2(*(__half2*)&w[c]);
                acc[base] += f.x;
                if (base + 1 < DR) acc[base + 1] += f.y;
            }
        }
    }
}

// Two threads per node (edge-split halves), degree-sorted order.
// Gather(half) + (h+agg)@W + b -> g_tmp(fp32), per-block BN partials.
template <int DR, int DP, int NLD>
__global__ void __launch_bounds__(256) k_gin(const float* __restrict__ W,
                                             const float* __restrict__ bias) {
    __shared__ float sW[DR * HID];
    __shared__ float sb[HID];
    __shared__ float sws[8][HID];
    __shared__ float swq[8][HID];

    const __half* hin = (DR == IN_DIM) ? (const __half*)g_xh : (const __half*)g_hh;

    int t = threadIdx.x;
    for (int j = t; j < DR * HID; j += 256) sW[j] = W[j];
    if (t < HID) sb[t] = bias[t];
    __syncthreads();

    int slot = blockIdx.x * 128 + (t >> 1);
    int sub = t & 1;
    bool active = (slot < N_NODES);
    int i = g_perm[min(slot, N_NODES - 1)];
    int deg = active ? min(g_cur[i], CAP) : 0;
    const int* sp = g_src + (size_t)i * CAP;

    float acc[DR];
#pragma unroll
    for (int d = 0; d < DR; d++) acc[d] = 0.f;

    int m = ((deg >> 1) + 3) & ~3;
    if (m > deg) m = deg;
    int kbeg = sub ? m : 0;
    int kend = sub ? deg : m;
    for (int k = kbeg; k < kend; k += 4) {
        int4 idx = *(const int4*)(sp + k);
        int id[4] = {idx.x, idx.y, idx.z, idx.w};
#pragma unroll
        for (int j = 0; j < 4; j++)
            if (k + j < kend) add_row<DR, DP, NLD>(acc, hin, id[j]);
    }
    if (sub == 0 && active) add_row<DR, DP, NLD>(acc, hin, i);  // own row (eps=0)

    // combine partner's partial into sub0
#pragma unroll
    for (int d = 0; d < DR; d++)
        acc[d] += __shfl_down_sync(0xffffffffu, acc[d], 1);

    float y[HID];
#pragma unroll
    for (int j = 0; j < HID; j++) y[j] = 0.f;
    if (sub == 0 && active) {
#pragma unroll
        for (int j = 0; j < HID; j++) {
            float v = sb[j];
#pragma unroll
            for (int d = 0; d < DR; d++) v += acc[d] * sW[d * HID + j];
            y[j] = v;
        }
        float4* tp = (float4*)(g_tmp + (size_t)i * HID);
#pragma unroll
        for (int j = 0; j < 5; j++)
            tp[j] = make_float4(y[4*j], y[4*j+1], y[4*j+2], y[4*j+3]);
    }

    // BN stats: warp shfl -> shared -> per-block float partials
    int lane = t & 31, wwid = t >> 5;
#pragma unroll
    for (int j = 0; j < HID; j++) {
        float s = y[j], q = y[j] * y[j];
#pragma unroll
        for (int o = 16; o; o >>= 1) {
            s += __shfl_down_sync(0xffffffff, s, o);
            q += __shfl_down_sync(0xffffffff, q, o);
        }
        if (lane == 0) { sws[wwid][j] = s; swq[wwid][j] = q; }
    }
    __syncthreads();
    if (t < HID) {
        float s = 0.f, q = 0.f;
#pragma unroll
        for (int w = 0; w < 8; w++) { s += sws[w][t]; q += swq[w][t]; }
        g_bsum[blockIdx.x * HID + t] = s;
        g_bsq[blockIdx.x * HID + t]  = q;
    }
}

// parallel partial reduce: warp w handles channel w
__global__ void k_finalize(const float* __restrict__ g, const float* __restrict__ beta, int nblk) {
    int w = threadIdx.x >> 5, lane = threadIdx.x & 31;
    if (w >= HID) return;
    double s = 0.0, q = 0.0;
    for (int b = lane; b < nblk; b += 32) {
        s += (double)g_bsum[b * HID + w];
        q += (double)g_bsq[b * HID + w];
    }
#pragma unroll
    for (int o = 16; o; o >>= 1) {
        s += __shfl_down_sync(0xffffffff, s, o);
        q += __shfl_down_sync(0xffffffff, q, o);
    }
    if (lane == 0) {
        float mu  = (float)(s / (double)N_NODES);
        float var = (float)(q / (double)N_NODES) - mu * mu;
        float a = rsqrtf(var + BN_EPS) * g[w];
        g_ab[w] = a;
        g_ab[HID + w] = beta[w] - mu * a;
    }
}

// normalize + relu -> half rows, stride 32 halfs (write 24, rest never read)
__global__ void k_norm() {
    int i = blockIdx.x * blockDim.x + threadIdx.x;
    if (i >= N_NODES) return;
    const float4* tp = (const float4*)(g_tmp + (size_t)i * HID);
    __half2 h[12];
#pragma unroll
    for (int q = 0; q < 5; q++) {
        float4 v = tp[q];
        int j = 4 * q;
        float r0 = fmaxf(v.x * g_ab[j+0] + g_ab[HID+j+0], 0.f);
        float r1 = fmaxf(v.y * g_ab[j+1] + g_ab[HID+j+1], 0.f);
        float r2 = fmaxf(v.z * g_ab[j+2] + g_ab[HID+j+2], 0.f);
        float r3 = fmaxf(v.w * g_ab[j+3] + g_ab[HID+j+3], 0.f);
        h[2*q]   = __floats2half2_rn(r0, r1);
        h[2*q+1] = __floats2half2_rn(r2, r3);
    }
    h[10] = __floats2half2_rn(0.f, 0.f);
    h[11] = __floats2half2_rn(0.f, 0.f);
    int4* op = (int4*)(g_hh + (size_t)i * 32);
    op[0] = *(int4*)&h[0];
    op[1] = *(int4*)&h[4];
    op[2] = *(int4*)&h[8];
}

// warp per graph: binary-search node range (batch sorted), norm+relu+pool+fc
__global__ void k_pool_fc(const int* __restrict__ batch,
                          const float* __restrict__ fcW, const float* __restrict__ fcb,
                          float* __restrict__ out) {
    int gid = (blockIdx.x * blockDim.x + threadIdx.x) >> 5;
    int lane = threadIdx.x & 31;
    if (gid >= N_GRAPHS) return;

    int lo = 0, hi = N_NODES;
    while (lo < hi) { int mid = (lo + hi) >> 1; if (batch[mid] < gid) lo = mid + 1; else hi = mid; }
    int r0 = lo;
    hi = N_NODES;
    while (lo < hi) { int mid = (lo + hi) >> 1; if (batch[mid] < gid + 1) lo = mid + 1; else hi = mid; }
    int r1 = lo;

    float a = 0.f, b = 0.f, w0 = 0.f, w1 = 0.f;
    if (lane < HID) {
        a = g_ab[lane]; b = g_ab[HID + lane];
        w0 = fcW[lane * 2 + 0]; w1 = fcW[lane * 2 + 1];
    }
    float p0 = 0.f, p1 = 0.f;
    int n = r0;
    for (; n + 2 <= r1; n += 2) {
        float v0 = (lane < HID) ? g_tmp[(size_t)n * HID + lane] * a + b : 0.f;
        float v1 = (lane < HID) ? g_tmp[(size_t)(n + 1) * HID + lane] * a + b : 0.f;
        p0 += fmaxf(v0, 0.f);
        p1 += fmaxf(v1, 0.f);
    }
    if (n < r1) {
        float v = (lane < HID) ? g_tmp[(size_t)n * HID + lane] * a + b : 0.f;
        p0 += fmaxf(v, 0.f);
    }
    float pool = p0 + p1;
    float o0 = pool * w0, o1 = pool * w1;
#pragma unroll
    for (int o = 16; o; o >>= 1) {
        o0 += __shfl_down_sync(0xffffffff, o0, o);
        o1 += __shfl_down_sync(0xffffffff, o1, o);
    }
    if (lane == 0) {
        out[gid * 2 + 0] = o0 + fcb[0];
        out[gid * 2 + 1] = o1 + fcb[1];
    }
}

extern "C" void kernel_launch(void* const* d_in, const int* in_sizes, int n_in,
                              void* d_out, int out_size) {
    const float* x     = (const float*)d_in[0];
    const int*   ei    = (const int*)d_in[1];
    const int*   batch = (const int*)d_in[2];
    const float* W1  = (const float*)d_in[3];
    const float* b1  = (const float*)d_in[4];
    const float* g1  = (const float*)d_in[5];
    const float* be1 = (const float*)d_in[6];
    const float* W2  = (const float*)d_in[7];
    const float* b2  = (const float*)d_in[8];
    const float* g2  = (const float*)d_in[9];
    const float* be2 = (const float*)d_in[10];
    const float* W3  = (const float*)d_in[11];
    const float* b3  = (const float*)d_in[12];
    const float* g3  = (const float*)d_in[13];
    const float* be3 = (const float*)d_in[14];
    const float* fcW = (const float*)d_in[15];
    const float* fcb = (const float*)d_in[16];
    float* out = (float*)d_out;

    k_zero_cur<<<NBLK_N, 256>>>();
    k_fill4<<<(N_EDGES / 4 + 255) / 256, 256>>>(ei);
    k_x2h<<<NBLK_N, 256>>>(x);
    k_hist<<<NBLK_N, 256>>>();
    k_scan<<<1, 32>>>();
    k_scatter<<<NBLK_N, 256>>>();

    // layer 1 (g_xh: 32B rows, 2 int4 loads)
    k_gin<IN_DIM, 16, 2><<<NBLK2, 256>>>(W1, b1);
    k_finalize<<<1, 640>>>(g1, be1, NBLK2);
    k_norm<<<NBLK_N, 256>>>();

    // layer 2 (g_hh: 64B stride, 3 int4 loads)
    k_gin<HID, 32, 3><<<NBLK2, 256>>>(W2, b2);
    k_finalize<<<1, 640>>>(g2, be2, NBLK2);
    k_norm<<<NBLK_N, 256>>>();

    // layer 3
    k_gin<HID, 32, 3><<<NBLK2, 256>>>(W3, b3);
    k_finalize<<<1, 640>>>(g3, be3, NBLK2);

    // norm + pool + fc fused (batch sorted -> contiguous ranges)
    k_pool_fc<<<(N_GRAPHS * 32 + 255) / 256, 256>>>(batch, fcW, fcb, out);
}

// round 10
// speedup vs baseline: 1.2398x; 1.0253x over previous
#include <cuda_runtime.h>
#include <cuda_fp16.h>

#define N_NODES 100000
#define N_EDGES 3200000
#define N_GRAPHS 1000
#define IN_DIM 10
#define HID 20
#define CAP 96
#define BN_EPS 1e-5f

#define NBLK_N ((N_NODES + 255) / 256)     // 391
#define NBLK2  ((N_NODES * 2 + 255) / 256) // 782 gin blocks (2 threads/node)

// ---- device scratch ----
__device__ int g_cur[N_NODES];
__device__ __align__(16)  int    g_src[N_NODES * CAP];   // row-major: g_src[i*CAP + k]
__device__ __align__(128) __half g_xh[N_NODES * 16];     // x half rows, 10 -> 16 (32B)
__device__ __align__(128) __half g_hh[N_NODES * 32];     // h half rows, stride 32 halfs (64B)
__device__ __align__(16)  float  g_tmp[N_NODES * HID];   // pre-BN activations (fp32)
__device__ float g_bsum[NBLK2 * HID];
__device__ float g_bsq[NBLK2 * HID];

// zero degree counters + convert x to padded half rows (fused)
__global__ void __launch_bounds__(256) k_prep(const float* __restrict__ x) {
    int i = blockIdx.x * 256 + threadIdx.x;
    if (i >= N_NODES) return;
    g_cur[i] = 0;
    const float2* xp = (const float2*)(x + (size_t)i * IN_DIM);
    __half2 h[8];
#pragma unroll
    for (int q = 0; q < 5; q++) { float2 v = xp[q]; h[q] = __floats2half2_rn(v.x, v.y); }
#pragma unroll
    for (int q = 5; q < 8; q++) h[q] = __floats2half2_rn(0.f, 0.f);
    int4* op = (int4*)(g_xh + (size_t)i * 16);
    op[0] = *(int4*)&h[0];
    op[1] = *(int4*)&h[4];
}

// 4 edges per thread via int4 loads
__global__ void __launch_bounds__(256) k_fill4(const int* __restrict__ ei) {
    int e4 = blockIdx.x * 256 + threadIdx.x;
    if (e4 * 4 >= N_EDGES) return;
    int4 s4 = ((const int4*)ei)[e4];
    int4 d4 = ((const int4*)(ei + N_EDGES))[e4];
    int ss[4] = {s4.x, s4.y, s4.z, s4.w};
    int dd[4] = {d4.x, d4.y, d4.z, d4.w};
#pragma unroll
    for (int q = 0; q < 4; q++) {
        int s = min(max(ss[q], 0), N_NODES - 1);
        int d = min(max(dd[q], 0), N_NODES - 1);
        int p = atomicAdd(&g_cur[d], 1);
        if (p < CAP) g_src[d * CAP + p] = s;
    }
}

template <int DR, int DP, int NLD>
__device__ __forceinline__ void add_row(float* acc, const __half* __restrict__ hin, int s) {
#pragma unroll
    for (int q = 0; q < NLD; q++) {
        int4 v = *(const int4*)(hin + (size_t)s * DP + q * 8);
        int w[4] = {v.x, v.y, v.z, v.w};
#pragma unroll
        for (int c = 0; c < 4; c++) {
            int base = q * 8 + c * 2;
            if (base < DR) {
                float2 f = __half22float2(*(__half2*)&w[c]);
                acc[base] += f.x;
                if (base + 1 < DR) acc[base + 1] += f.y;
            }
        }
    }
}

// Two threads per node (edge-split halves).
// Gather(half) + (h+agg)@W + b -> g_tmp(fp32), per-block BN partials.
template <int DR, int DP, int NLD>
__global__ void __launch_bounds__(256) k_gin(const float* __restrict__ W,
                                             const float* __restrict__ bias) {
    __shared__ float sW[DR * HID];
    __shared__ float sb[HID];
    __shared__ float sws[8][HID];
    __shared__ float swq[8][HID];

    const __half* hin = (DR == IN_DIM) ? (const __half*)g_xh : (const __half*)g_hh;

    int t = threadIdx.x;
    for (int j = t; j < DR * HID; j += 256) sW[j] = W[j];
    if (t < HID) sb[t] = bias[t];
    __syncthreads();

    int i = blockIdx.x * 128 + (t >> 1);
    int sub = t & 1;
    bool active = (i < N_NODES);
    int ii = min(i, N_NODES - 1);
    int deg = active ? min(g_cur[ii], CAP) : 0;
    const int* sp = g_src + (size_t)ii * CAP;

    float acc[DR];
#pragma unroll
    for (int d = 0; d < DR; d++) acc[d] = 0.f;

    int m = ((deg >> 1) + 3) & ~3;     // 16B-aligned split point
    if (m > deg) m = deg;
    int kbeg = sub ? m : 0;
    int kend = sub ? deg : m;
    for (int k = kbeg; k < kend; k += 4) {
        int4 idx = *(const int4*)(sp + k);
        int id[4] = {idx.x, idx.y, idx.z, idx.w};
#pragma unroll
        for (int j = 0; j < 4; j++)
            if (k + j < kend) add_row<DR, DP, NLD>(acc, hin, id[j]);
    }
    if (sub == 0 && active) add_row<DR, DP, NLD>(acc, hin, ii);  // own row (eps=0)

    // combine partner's partial into sub0
#pragma unroll
    for (int d = 0; d < DR; d++)
        acc[d] += __shfl_down_sync(0xffffffffu, acc[d], 1);

    float y[HID];
#pragma unroll
    for (int j = 0; j < HID; j++) y[j] = 0.f;
    if (sub == 0 && active) {
#pragma unroll
        for (int j = 0; j < HID; j++) {
            float v = sb[j];
#pragma unroll
            for (int d = 0; d < DR; d++) v += acc[d] * sW[d * HID + j];
            y[j] = v;
        }
        float4* tp = (float4*)(g_tmp + (size_t)i * HID);
#pragma unroll
        for (int j = 0; j < 5; j++)
            tp[j] = make_float4(y[4*j], y[4*j+1], y[4*j+2], y[4*j+3]);
    }

    // BN stats: warp shfl -> shared -> per-block float partials
    int lane = t & 31, wwid = t >> 5;
#pragma unroll
    for (int j = 0; j < HID; j++) {
        float s = y[j], q = y[j] * y[j];
#pragma unroll
        for (int o = 16; o; o >>= 1) {
            s += __shfl_down_sync(0xffffffff, s, o);
            q += __shfl_down_sync(0xffffffff, q, o);
        }
        if (lane == 0) { sws[wwid][j] = s; swq[wwid][j] = q; }
    }
    __syncthreads();
    if (t < HID) {
        float s = 0.f, q = 0.f;
#pragma unroll
        for (int w = 0; w < 8; w++) { s += sws[w][t]; q += swq[w][t]; }
        g_bsum[blockIdx.x * HID + t] = s;
        g_bsq[blockIdx.x * HID + t]  = q;
    }
}

// Fused BN-finalize + normalize + relu -> g_hh.
// Phase 1: 20 warps redundantly reduce the NBLK2 partials (per block).
// Phase 2: thread-per-node normalize (640 nodes per block).
__global__ void __launch_bounds__(640) k_bnorm(const float* __restrict__ g,
                                               const float* __restrict__ beta) {
    __shared__ float sab[2 * HID];
    int w = threadIdx.x >> 5, lane = threadIdx.x & 31;
    if (w < HID) {
        double s = 0.0, q = 0.0;
        for (int b = lane; b < NBLK2; b += 32) {
            s += (double)g_bsum[b * HID + w];
            q += (double)g_bsq[b * HID + w];
        }
#pragma unroll
        for (int o = 16; o; o >>= 1) {
            s += __shfl_down_sync(0xffffffff, s, o);
            q += __shfl_down_sync(0xffffffff, q, o);
        }
        if (lane == 0) {
            float mu  = (float)(s / (double)N_NODES);
            float var = (float)(q / (double)N_NODES) - mu * mu;
            float a = rsqrtf(var + BN_EPS) * g[w];
            sab[w] = a;
            sab[HID + w] = beta[w] - mu * a;
        }
    }
    __syncthreads();

    int i = blockIdx.x * 640 + threadIdx.x;
    if (i >= N_NODES) return;
    const float4* tp = (const float4*)(g_tmp + (size_t)i * HID);
    __half2 h[12];
#pragma unroll
    for (int q = 0; q < 5; q++) {
        float4 v = tp[q];
        int j = 4 * q;
        float r0 = fmaxf(v.x * sab[j+0] + sab[HID+j+0], 0.f);
        float r1 = fmaxf(v.y * sab[j+1] + sab[HID+j+1], 0.f);
        float r2 = fmaxf(v.z * sab[j+2] + sab[HID+j+2], 0.f);
        float r3 = fmaxf(v.w * sab[j+3] + sab[HID+j+3], 0.f);
        h[2*q]   = __floats2half2_rn(r0, r1);
        h[2*q+1] = __floats2half2_rn(r2, r3);
    }
    h[10] = __floats2half2_rn(0.f, 0.f);
    h[11] = __floats2half2_rn(0.f, 0.f);
    int4* op = (int4*)(g_hh + (size_t)i * 32);
    op[0] = *(int4*)&h[0];
    op[1] = *(int4*)&h[4];
    op[2] = *(int4*)&h[8];
}

// Fused BN-finalize (layer 3) + norm + relu + pool + fc.
// Phase 1: reduce partials (as k_bnorm). Phase 2: warp per graph (20 per block).
__global__ void __launch_bounds__(640) k_poolfc(const float* __restrict__ g,
                                                const float* __restrict__ beta,
                                                const int* __restrict__ batch,
                                                const float* __restrict__ fcW,
                                                const float* __restrict__ fcb,
                                                float* __restrict__ out) {
    __shared__ float sab[2 * HID];
    int w = threadIdx.x >> 5, lane = threadIdx.x & 31;
    if (w < HID) {
        double s = 0.0, q = 0.0;
        for (int b = lane; b < NBLK2; b += 32) {
            s += (double)g_bsum[b * HID + w];
            q += (double)g_bsq[b * HID + w];
        }
#pragma unroll
        for (int o = 16; o; o >>= 1) {
            s += __shfl_down_sync(0xffffffff, s, o);
            q += __shfl_down_sync(0xffffffff, q, o);
        }
        if (lane == 0) {
            float mu  = (float)(s / (double)N_NODES);
            float var = (float)(q / (double)N_NODES) - mu * mu;
            float a = rsqrtf(var + BN_EPS) * g[w];
            sab[w] = a;
            sab[HID + w] = beta[w] - mu * a;
        }
    }
    __syncthreads();

    int gid = blockIdx.x * 20 + w;
    if (gid >= N_GRAPHS) return;

    int lo = 0, hi = N_NODES;
    while (lo < hi) { int mid = (lo + hi) >> 1; if (batch[mid] < gid) lo = mid + 1; else hi = mid; }
    int r0 = lo;
    hi = N_NODES;
    while (lo < hi) { int mid = (lo + hi) >> 1; if (batch[mid] < gid + 1) lo = mid + 1; else hi = mid; }
    int r1 = lo;

    float a = 0.f, b = 0.f, w0 = 0.f, w1 = 0.f;
    if (lane < HID) {
        a = sab[lane]; b = sab[HID + lane];
        w0 = fcW[lane * 2 + 0]; w1 = fcW[lane * 2 + 1];
    }
    float p0 = 0.f, p1 = 0.f;
    int n = r0;
    for (; n + 2 <= r1; n += 2) {
        float v0 = (lane < HID) ? g_tmp[(size_t)n * HID + lane] * a + b : 0.f;
        float v1 = (lane < HID) ? g_tmp[(size_t)(n + 1) * HID + lane] * a + b : 0.f;
        p0 += fmaxf(v0, 0.f);
        p1 += fmaxf(v1, 0.f);
    }
    if (n < r1) {
        float v = (lane < HID) ? g_tmp[(size_t)n * HID + lane] * a + b : 0.f;
        p0 += fmaxf(v, 0.f);
    }
    float pool = p0 + p1;
    float o0 = pool * w0, o1 = pool * w1;
#pragma unroll
    for (int o = 16; o; o >>= 1) {
        o0 += __shfl_down_sync(0xffffffff, o0, o);
        o1 += __shfl_down_sync(0xffffffff, o1, o);
    }
    if (lane == 0) {
        out[gid * 2 + 0] = o0 + fcb[0];
        out[gid * 2 + 1] = o1 + fcb[1];
    }
}

extern "C" void kernel_launch(void* const* d_in, const int* in_sizes, int n_in,
                              void* d_out, int out_size) {
    const float* x     = (const float*)d_in[0];
    const int*   ei    = (const int*)d_in[1];
    const int*   batch = (const int*)d_in[2];
    const float* W1  = (const float*)d_in[3];
    const float* b1  = (const float*)d_in[4];
    const float* g1  = (const float*)d_in[5];
    const float* be1 = (const float*)d_in[6];
    const float* W2  = (const float*)d_in[7];
    const float* b2  = (const float*)d_in[8];
    const float* g2  = (const float*)d_in[9];
    const float* be2 = (const float*)d_in[10];
    const float* W3  = (const float*)d_in[11];
    const float* b3  = (const float*)d_in[12];
    const float* g3  = (const float*)d_in[13];
    const float* be3 = (const float*)d_in[14];
    const float* fcW = (const float*)d_in[15];
    const float* fcb = (const float*)d_in[16];
    float* out = (float*)d_out;

    const int NBNORM = (N_NODES + 639) / 640;       // 157
    const int NPF    = (N_GRAPHS + 19) / 20;        // 50

    k_prep<<<NBLK_N, 256>>>(x);                      // zero g_cur + x -> half
    k_fill4<<<(N_EDGES / 4 + 255) / 256, 256>>>(ei); // reverse adjacency

    k_gin<IN_DIM, 16, 2><<<NBLK2, 256>>>(W1, b1);
    k_bnorm<<<NBNORM, 640>>>(g1, be1);

    k_gin<HID, 32, 3><<<NBLK2, 256>>>(W2, b2);
    k_bnorm<<<NBNORM, 640>>>(g2, be2);

    k_gin<HID, 32, 3><<<NBLK2, 256>>>(W3, b3);
    k_poolfc<<<NPF, 640>>>(g3, be3, batch, fcW, fcb, out);
}

// round 11
// speedup vs baseline: 1.8831x; 1.5189x over previous
#include <cuda_runtime.h>
#include <cuda_fp16.h>

#define N_NODES 100000
#define N_EDGES 3200000
#define N_GRAPHS 1000
#define IN_DIM 10
#define HID 20
#define CAP 96
#define BN_EPS 1e-5f

#define NBLK_N ((N_NODES + 255) / 256)     // 391
#define NBLK2  ((N_NODES * 2 + 255) / 256) // 782 gin blocks (2 threads/node)

// ---- device scratch ----
__device__ int g_cur[N_NODES];
__device__ __align__(16)  int    g_src[N_NODES * CAP];   // row-major: g_src[i*CAP + k]
__device__ __align__(128) __half g_xh[N_NODES * 16];     // x half rows, 10 -> 16 (32B)
__device__ __align__(128) __half g_hh[N_NODES * 32];     // h half rows, stride 32 halfs (64B)
__device__ __align__(16)  float  g_tmp[N_NODES * HID];   // pre-BN activations (fp32)
// transposed partials: [channel][block] -> coalesced reduce reads
__device__ __align__(16) float g_bsum[HID * NBLK2];
__device__ __align__(16) float g_bsq[HID * NBLK2];

// zero degree counters + convert x to padded half rows (fused)
__global__ void __launch_bounds__(256) k_prep(const float* __restrict__ x) {
    int i = blockIdx.x * 256 + threadIdx.x;
    if (i >= N_NODES) return;
    g_cur[i] = 0;
    const float2* xp = (const float2*)(x + (size_t)i * IN_DIM);
    __half2 h[8];
#pragma unroll
    for (int q = 0; q < 5; q++) { float2 v = xp[q]; h[q] = __floats2half2_rn(v.x, v.y); }
#pragma unroll
    for (int q = 5; q < 8; q++) h[q] = __floats2half2_rn(0.f, 0.f);
    int4* op = (int4*)(g_xh + (size_t)i * 16);
    op[0] = *(int4*)&h[0];
    op[1] = *(int4*)&h[4];
}

// 4 edges per thread via int4 loads
__global__ void __launch_bounds__(256) k_fill4(const int* __restrict__ ei) {
    int e4 = blockIdx.x * 256 + threadIdx.x;
    if (e4 * 4 >= N_EDGES) return;
    int4 s4 = ((const int4*)ei)[e4];
    int4 d4 = ((const int4*)(ei + N_EDGES))[e4];
    int ss[4] = {s4.x, s4.y, s4.z, s4.w};
    int dd[4] = {d4.x, d4.y, d4.z, d4.w};
#pragma unroll
    for (int q = 0; q < 4; q++) {
        int s = min(max(ss[q], 0), N_NODES - 1);
        int d = min(max(dd[q], 0), N_NODES - 1);
        int p = atomicAdd(&g_cur[d], 1);
        if (p < CAP) g_src[d * CAP + p] = s;
    }
}

template <int DR, int DP, int NLD>
__device__ __forceinline__ void add_row(float* acc, const __half* __restrict__ hin, int s) {
#pragma unroll
    for (int q = 0; q < NLD; q++) {
        int4 v = *(const int4*)(hin + (size_t)s * DP + q * 8);
        int w[4] = {v.x, v.y, v.z, v.w};
#pragma unroll
        for (int c = 0; c < 4; c++) {
            int base = q * 8 + c * 2;
            if (base < DR) {
                float2 f = __half22float2(*(__half2*)&w[c]);
                acc[base] += f.x;
                if (base + 1 < DR) acc[base + 1] += f.y;
            }
        }
    }
}

// Two threads per node (edge-split halves).
// Gather(half) + (h+agg)@W + b -> g_tmp(fp32), per-block BN partials (transposed).
template <int DR, int DP, int NLD>
__global__ void __launch_bounds__(256) k_gin(const float* __restrict__ W,
                                             const float* __restrict__ bias) {
    __shared__ float sW[DR * HID];
    __shared__ float sb[HID];
    __shared__ float sws[8][HID];
    __shared__ float swq[8][HID];

    const __half* hin = (DR == IN_DIM) ? (const __half*)g_xh : (const __half*)g_hh;

    int t = threadIdx.x;
    for (int j = t; j < DR * HID; j += 256) sW[j] = W[j];
    if (t < HID) sb[t] = bias[t];
    __syncthreads();

    int i = blockIdx.x * 128 + (t >> 1);
    int sub = t & 1;
    bool active = (i < N_NODES);
    int ii = min(i, N_NODES - 1);
    int deg = active ? min(g_cur[ii], CAP) : 0;
    const int* sp = g_src + (size_t)ii * CAP;

    float acc[DR];
#pragma unroll
    for (int d = 0; d < DR; d++) acc[d] = 0.f;

    int m = ((deg >> 1) + 3) & ~3;     // 16B-aligned split point
    if (m > deg) m = deg;
    int kbeg = sub ? m : 0;
    int kend = sub ? deg : m;
    for (int k = kbeg; k < kend; k += 4) {
        int4 idx = *(const int4*)(sp + k);
        int id[4] = {idx.x, idx.y, idx.z, idx.w};
#pragma unroll
        for (int j = 0; j < 4; j++)
            if (k + j < kend) add_row<DR, DP, NLD>(acc, hin, id[j]);
    }
    if (sub == 0 && active) add_row<DR, DP, NLD>(acc, hin, ii);  // own row (eps=0)

    // combine partner's partial into sub0
#pragma unroll
    for (int d = 0; d < DR; d++)
        acc[d] += __shfl_down_sync(0xffffffffu, acc[d], 1);

    float y[HID];
#pragma unroll
    for (int j = 0; j < HID; j++) y[j] = 0.f;
    if (sub == 0 && active) {
#pragma unroll
        for (int j = 0; j < HID; j++) {
            float v = sb[j];
#pragma unroll
            for (int d = 0; d < DR; d++) v += acc[d] * sW[d * HID + j];
            y[j] = v;
        }
        float4* tp = (float4*)(g_tmp + (size_t)i * HID);
#pragma unroll
        for (int j = 0; j < 5; j++)
            tp[j] = make_float4(y[4*j], y[4*j+1], y[4*j+2], y[4*j+3]);
    }

    // BN stats: warp shfl -> shared -> per-block float partials (transposed layout)
    int lane = t & 31, wwid = t >> 5;
#pragma unroll
    for (int j = 0; j < HID; j++) {
        float s = y[j], q = y[j] * y[j];
#pragma unroll
        for (int o = 16; o; o >>= 1) {
            s += __shfl_down_sync(0xffffffff, s, o);
            q += __shfl_down_sync(0xffffffff, q, o);
        }
        if (lane == 0) { sws[wwid][j] = s; swq[wwid][j] = q; }
    }
    __syncthreads();
    if (t < HID) {
        float s = 0.f, q = 0.f;
#pragma unroll
        for (int w = 0; w < 8; w++) { s += sws[w][t]; q += swq[w][t]; }
        g_bsum[t * NBLK2 + blockIdx.x] = s;
        g_bsq[t * NBLK2 + blockIdx.x]  = q;
    }
}

// shared phase-1: warp w reduces channel w's NBLK2 partials (fp32, coalesced)
__device__ __forceinline__ void bn_reduce(float* sab, const float* __restrict__ g,
                                          const float* __restrict__ beta,
                                          int w, int lane) {
    if (w < HID) {
        float s = 0.f, q = 0.f;
        const float* bs = g_bsum + w * NBLK2;
        const float* bq = g_bsq + w * NBLK2;
        for (int b = lane; b < NBLK2; b += 32) { s += bs[b]; q += bq[b]; }
#pragma unroll
        for (int o = 16; o; o >>= 1) {
            s += __shfl_down_sync(0xffffffff, s, o);
            q += __shfl_down_sync(0xffffffff, q, o);
        }
        if (lane == 0) {
            float mu  = s / (float)N_NODES;
            float var = q / (float)N_NODES - mu * mu;
            float a = rsqrtf(var + BN_EPS) * g[w];
            sab[w] = a;
            sab[HID + w] = beta[w] - mu * a;
        }
    }
}

// Fused BN-finalize + normalize + relu -> g_hh.
__global__ void __launch_bounds__(640) k_bnorm(const float* __restrict__ g,
                                               const float* __restrict__ beta) {
    __shared__ float sab[2 * HID];
    bn_reduce(sab, g, beta, threadIdx.x >> 5, threadIdx.x & 31);
    __syncthreads();

    int i = blockIdx.x * 640 + threadIdx.x;
    if (i >= N_NODES) return;
    const float4* tp = (const float4*)(g_tmp + (size_t)i * HID);
    __half2 h[12];
#pragma unroll
    for (int q = 0; q < 5; q++) {
        float4 v = tp[q];
        int j = 4 * q;
        float r0 = fmaxf(v.x * sab[j+0] + sab[HID+j+0], 0.f);
        float r1 = fmaxf(v.y * sab[j+1] + sab[HID+j+1], 0.f);
        float r2 = fmaxf(v.z * sab[j+2] + sab[HID+j+2], 0.f);
        float r3 = fmaxf(v.w * sab[j+3] + sab[HID+j+3], 0.f);
        h[2*q]   = __floats2half2_rn(r0, r1);
        h[2*q+1] = __floats2half2_rn(r2, r3);
    }
    h[10] = __floats2half2_rn(0.f, 0.f);
    h[11] = __floats2half2_rn(0.f, 0.f);
    int4* op = (int4*)(g_hh + (size_t)i * 32);
    op[0] = *(int4*)&h[0];
    op[1] = *(int4*)&h[4];
    op[2] = *(int4*)&h[8];
}

// Fused BN-finalize (layer 3) + norm + relu + pool + fc. Warp per graph (20/block).
__global__ void __launch_bounds__(640) k_poolfc(const float* __restrict__ g,
                                                const float* __restrict__ beta,
                                                const int* __restrict__ batch,
                                                const float* __restrict__ fcW,
                                                const float* __restrict__ fcb,
                                                float* __restrict__ out) {
    __shared__ float sab[2 * HID];
    int w = threadIdx.x >> 5, lane = threadIdx.x & 31;
    bn_reduce(sab, g, beta, w, lane);
    __syncthreads();

    int gid = blockIdx.x * 20 + w;
    if (gid >= N_GRAPHS) return;

    int lo = 0, hi = N_NODES;
    while (lo < hi) { int mid = (lo + hi) >> 1; if (batch[mid] < gid) lo = mid + 1; else hi = mid; }
    int r0 = lo;
    hi = N_NODES;
    while (lo < hi) { int mid = (lo + hi) >> 1; if (batch[mid] < gid + 1) lo = mid + 1; else hi = mid; }
    int r1 = lo;

    float a = 0.f, b = 0.f, w0 = 0.f, w1 = 0.f;
    if (lane < HID) {
        a = sab[lane]; b = sab[HID + lane];
        w0 = fcW[lane * 2 + 0]; w1 = fcW[lane * 2 + 1];
    }
    float p0 = 0.f, p1 = 0.f;
    int n = r0;
    for (; n + 2 <= r1; n += 2) {
        float v0 = (lane < HID) ? g_tmp[(size_t)n * HID + lane] * a + b : 0.f;
        float v1 = (lane < HID) ? g_tmp[(size_t)(n + 1) * HID + lane] * a + b : 0.f;
        p0 += fmaxf(v0, 0.f);
        p1 += fmaxf(v1, 0.f);
    }
    if (n < r1) {
        float v = (lane < HID) ? g_tmp[(size_t)n * HID + lane] * a + b : 0.f;
        p0 += fmaxf(v, 0.f);
    }
    float pool = p0 + p1;
    float o0 = pool * w0, o1 = pool * w1;
#pragma unroll
    for (int o = 16; o; o >>= 1) {
        o0 += __shfl_down_sync(0xffffffff, o0, o);
        o1 += __shfl_down_sync(0xffffffff, o1, o);
    }
    if (lane == 0) {
        out[gid * 2 + 0] = o0 + fcb[0];
        out[gid * 2 + 1] = o1 + fcb[1];
    }
}

extern "C" void kernel_launch(void* const* d_in, const int* in_sizes, int n_in,
                              void* d_out, int out_size) {
    const float* x     = (const float*)d_in[0];
    const int*   ei    = (const int*)d_in[1];
    const int*   batch = (const int*)d_in[2];
    const float* W1  = (const float*)d_in[3];
    const float* b1  = (const float*)d_in[4];
    const float* g1  = (const float*)d_in[5];
    const float* be1 = (const float*)d_in[6];
    const float* W2  = (const float*)d_in[7];
    const float* b2  = (const float*)d_in[8];
    const float* g2  = (const float*)d_in[9];
    const float* be2 = (const float*)d_in[10];
    const float* W3  = (const float*)d_in[11];
    const float* b3  = (const float*)d_in[12];
    const float* g3  = (const float*)d_in[13];
    const float* be3 = (const float*)d_in[14];
    const float* fcW = (const float*)d_in[15];
    const float* fcb = (const float*)d_in[16];
    float* out = (float*)d_out;

    const int NBNORM = (N_NODES + 639) / 640;       // 157
    const int NPF    = (N_GRAPHS + 19) / 20;        // 50

    k_prep<<<NBLK_N, 256>>>(x);                      // zero g_cur + x -> half
    k_fill4<<<(N_EDGES / 4 + 255) / 256, 256>>>(ei); // reverse adjacency

    k_gin<IN_DIM, 16, 2><<<NBLK2, 256>>>(W1, b1);
    k_bnorm<<<NBNORM, 640>>>(g1, be1);

    k_gin<HID, 32, 3><<<NBLK2, 256>>>(W2, b2);
    k_bnorm<<<NBNORM, 640>>>(g2, be2);

    k_gin<HID, 32, 3><<<NBLK2, 256>>>(W3, b3);
    k_poolfc<<<NPF, 640>>>(g3, be3, batch, fcW, fcb, out);
}